// round 1
// baseline (speedup 1.0000x reference)
#include <cuda_runtime.h>
#include <cstdint>

#define H_HEADS 16
#define DHEAD 128
#define SEQ 2048
#define BATCH 2
#define CDIM 2048
#define WIN 256

// Scratch (no allocation allowed): Q,K,V in (B,H,L,D), attn output in (B,L,C)
__device__ float g_q[(size_t)BATCH * H_HEADS * SEQ * DHEAD];
__device__ float g_k[(size_t)BATCH * H_HEADS * SEQ * DHEAD];
__device__ float g_v[(size_t)BATCH * H_HEADS * SEQ * DHEAD];
__device__ float g_ao[(size_t)BATCH * SEQ * CDIM];

__device__ __forceinline__ uint32_t f2tf(float x) {
    uint32_t r;
    asm("cvt.rna.tf32.f32 %0, %1;" : "=r"(r) : "f"(x));
    return r;
}

__device__ __forceinline__ void mma8(float* c, const uint32_t* a, uint32_t b0, uint32_t b1) {
    asm volatile(
        "mma.sync.aligned.m16n8k8.row.col.f32.tf32.tf32.f32 "
        "{%0,%1,%2,%3},{%4,%5,%6,%7},{%8,%9},{%0,%1,%2,%3};\n"
        : "+f"(c[0]), "+f"(c[1]), "+f"(c[2]), "+f"(c[3])
        : "r"(a[0]), "r"(a[1]), "r"(a[2]), "r"(a[3]), "r"(b0), "r"(b1));
}

__device__ __forceinline__ void cp16(void* dst, const void* src) {
    uint32_t d = (uint32_t)__cvta_generic_to_shared(dst);
    asm volatile("cp.async.cg.shared.global [%0], [%1], 16;\n" :: "r"(d), "l"(src));
}
__device__ __forceinline__ void cp_commit() { asm volatile("cp.async.commit_group;\n"); }
template<int N> __device__ __forceinline__ void cp_wait() {
    asm volatile("cp.async.wait_group %0;\n" :: "n"(N));
}

// ---------------------------------------------------------------------------
// GEMM: out[m,n] = sum_k A[m,k] * W[n,k] + bias[n]   (torch Linear, TN)
// mode 0: out row-major (M x N).  mode 1: scatter to (B,H,L,D).
// ---------------------------------------------------------------------------
#define GBM 128
#define GBN 128
#define GBK 16
#define GSTR 20

__global__ __launch_bounds__(256, 2)
void gemm_tf32(const float* __restrict__ A, const float* __restrict__ W,
               const float* __restrict__ bias, float* __restrict__ out,
               int M, int N, int K, int mode)
{
    __shared__ float As[2][GBM][GSTR];
    __shared__ float Bs[2][GBN][GSTR];
    int tid = threadIdx.x;
    int wid = tid >> 5, lane = tid & 31;
    int g = lane >> 2, tg = lane & 3;
    int wm = wid >> 1, wn = wid & 1;
    int m0 = blockIdx.x * GBM;
    int n0 = blockIdx.y * GBN;

    float acc[2][8][4];
    #pragma unroll
    for (int mt = 0; mt < 2; mt++)
        #pragma unroll
        for (int nt = 0; nt < 8; nt++)
            #pragma unroll
            for (int i = 0; i < 4; i++) acc[mt][nt][i] = 0.f;

    const int KT = K / GBK;

    // prefetch tile 0
    {
        int bk = 0;
        #pragma unroll
        for (int e = tid; e < GBM * 4; e += 256) {
            int r = e >> 2, c4 = e & 3;
            cp16(&As[0][r][c4 * 4], &A[(size_t)(m0 + r) * K + bk + c4 * 4]);
            cp16(&Bs[0][r][c4 * 4], &W[(size_t)(n0 + r) * K + bk + c4 * 4]);
        }
        cp_commit();
    }

    for (int kt = 0; kt < KT; kt++) {
        int buf = kt & 1;
        if (kt + 1 < KT) {
            int bk = (kt + 1) * GBK;
            int nb = (kt + 1) & 1;
            #pragma unroll
            for (int e = tid; e < GBM * 4; e += 256) {
                int r = e >> 2, c4 = e & 3;
                cp16(&As[nb][r][c4 * 4], &A[(size_t)(m0 + r) * K + bk + c4 * 4]);
                cp16(&Bs[nb][r][c4 * 4], &W[(size_t)(n0 + r) * K + bk + c4 * 4]);
            }
            cp_commit();
            cp_wait<1>();
        } else {
            cp_wait<0>();
        }
        __syncthreads();

        #pragma unroll
        for (int ks = 0; ks < 2; ks++) {
            uint32_t a[2][4];
            int c = ks * 8 + tg;
            #pragma unroll
            for (int mt = 0; mt < 2; mt++) {
                int r = wm * 32 + mt * 16 + g;
                a[mt][0] = f2tf(As[buf][r][c]);
                a[mt][1] = f2tf(As[buf][r + 8][c]);
                a[mt][2] = f2tf(As[buf][r][c + 4]);
                a[mt][3] = f2tf(As[buf][r + 8][c + 4]);
            }
            #pragma unroll
            for (int nt = 0; nt < 8; nt++) {
                int n = wn * 64 + nt * 8 + g;
                uint32_t b0 = f2tf(Bs[buf][n][c]);
                uint32_t b1 = f2tf(Bs[buf][n][c + 4]);
                mma8(acc[0][nt], a[0], b0, b1);
                mma8(acc[1][nt], a[1], b0, b1);
            }
        }
        __syncthreads();
    }

    // epilogue
    #pragma unroll
    for (int mt = 0; mt < 2; mt++) {
        #pragma unroll
        for (int nt = 0; nt < 8; nt++) {
            int r0 = m0 + wm * 32 + mt * 16 + g;
            int c0 = n0 + wn * 64 + nt * 8 + 2 * tg;
            float bv0 = bias[c0], bv1 = bias[c0 + 1];
            float v00 = acc[mt][nt][0] + bv0, v01 = acc[mt][nt][1] + bv1;
            float v10 = acc[mt][nt][2] + bv0, v11 = acc[mt][nt][3] + bv1;
            if (mode == 0) {
                *(float2*)&out[(size_t)r0 * N + c0]       = make_float2(v00, v01);
                *(float2*)&out[(size_t)(r0 + 8) * N + c0] = make_float2(v10, v11);
            } else {
                int b = r0 >> 11, l = r0 & 2047;
                int h = c0 >> 7, d = c0 & 127;
                size_t base = ((size_t)(b * H_HEADS + h) * SEQ + l) * DHEAD + d;
                *(float2*)&out[base]                       = make_float2(v00, v01);
                *(float2*)&out[base + (size_t)8 * DHEAD]   = make_float2(v10, v11);
            }
        }
    }
}

// ---------------------------------------------------------------------------
// Sliding-window flash attention. grid (L/128, B*H), 256 threads.
// Each warp owns 16 query rows; 64-key chunks; diagonal chunk processed first
// so the running max is finite before fully-masked chunks.
// ---------------------------------------------------------------------------
#define KSTR 132
#define VSTR 136
#define SSTR 68
#define ATT_SMEM ((64 * KSTR + 64 * VSTR + 128 * SSTR) * 4)

__global__ __launch_bounds__(256, 1)
void attn_win(const float* __restrict__ qg, const float* __restrict__ kg,
              const float* __restrict__ vg, float* __restrict__ aout)
{
    extern __shared__ float sm[];
    float* Ks = sm;
    float* Vs = sm + 64 * KSTR;
    float* Ss = Vs + 64 * VSTR;

    int tid = threadIdx.x;
    int wid = tid >> 5, lane = tid & 31, g = lane >> 2, tg = lane & 3;
    int q0 = blockIdx.x * 128;
    int bh = blockIdx.y;
    const float* qb = qg + (size_t)bh * SEQ * DHEAD;
    const float* kb = kg + (size_t)bh * SEQ * DHEAD;
    const float* vb = vg + (size_t)bh * SEQ * DHEAD;
    int b = bh >> 4, h = bh & 15;

    // Q fragments kept in registers for all chunks
    uint32_t qa[16][4];
    int qr = q0 + wid * 16 + g;
    #pragma unroll
    for (int ks = 0; ks < 16; ks++) {
        int c = ks * 8 + tg;
        qa[ks][0] = f2tf(__ldg(&qb[(size_t)qr * DHEAD + c]));
        qa[ks][1] = f2tf(__ldg(&qb[(size_t)(qr + 8) * DHEAD + c]));
        qa[ks][2] = f2tf(__ldg(&qb[(size_t)qr * DHEAD + c + 4]));
        qa[ks][3] = f2tf(__ldg(&qb[(size_t)(qr + 8) * DHEAD + c + 4]));
    }

    float o[16][4];
    #pragma unroll
    for (int nt = 0; nt < 16; nt++)
        #pragma unroll
        for (int i = 0; i < 4; i++) o[nt][i] = 0.f;
    float mrow0 = -1e30f, mrow1 = -1e30f, lsum0 = 0.f, lsum1 = 0.f;

    const float scale = 0.088388347648318447f;  // 1/sqrt(128)
    const int offs[6] = {0, 1, -1, -2, -3, -4}; // diagonal chunk FIRST

    for (int ci = 0; ci < 6; ci++) {
        int k0 = q0 + offs[ci] * 64;
        if (k0 < 0) continue;
        __syncthreads();
        #pragma unroll
        for (int e = tid; e < 64 * 32; e += 256) {
            int r = e >> 5, c4 = e & 31;
            *(float4*)&Ks[r * KSTR + c4 * 4] = *(const float4*)&kb[(size_t)(k0 + r) * DHEAD + c4 * 4];
            *(float4*)&Vs[r * VSTR + c4 * 4] = *(const float4*)&vb[(size_t)(k0 + r) * DHEAD + c4 * 4];
        }
        __syncthreads();

        // S = Q K^T  (16 rows x 64 keys per warp)
        float s[8][4];
        #pragma unroll
        for (int nt = 0; nt < 8; nt++)
            #pragma unroll
            for (int i = 0; i < 4; i++) s[nt][i] = 0.f;
        #pragma unroll
        for (int ks = 0; ks < 16; ks++) {
            int c = ks * 8 + tg;
            #pragma unroll
            for (int nt = 0; nt < 8; nt++) {
                int n = nt * 8 + g;
                uint32_t b0 = f2tf(Ks[n * KSTR + c]);
                uint32_t b1 = f2tf(Ks[n * KSTR + c + 4]);
                mma8(s[nt], qa[ks], b0, b1);
            }
        }

        // scale + mask + row max
        int i0 = q0 + wid * 16 + g, i1 = i0 + 8;
        float mx0 = -1e30f, mx1 = -1e30f;
        #pragma unroll
        for (int nt = 0; nt < 8; nt++) {
            int j0 = k0 + nt * 8 + 2 * tg, j1 = j0 + 1;
            s[nt][0] = ((j0 <= i0) && (j0 > i0 - WIN)) ? s[nt][0] * scale : -1e30f;
            s[nt][1] = ((j1 <= i0) && (j1 > i0 - WIN)) ? s[nt][1] * scale : -1e30f;
            s[nt][2] = ((j0 <= i1) && (j0 > i1 - WIN)) ? s[nt][2] * scale : -1e30f;
            s[nt][3] = ((j1 <= i1) && (j1 > i1 - WIN)) ? s[nt][3] * scale : -1e30f;
            mx0 = fmaxf(mx0, fmaxf(s[nt][0], s[nt][1]));
            mx1 = fmaxf(mx1, fmaxf(s[nt][2], s[nt][3]));
        }
        mx0 = fmaxf(mx0, __shfl_xor_sync(0xffffffffu, mx0, 1));
        mx0 = fmaxf(mx0, __shfl_xor_sync(0xffffffffu, mx0, 2));
        mx1 = fmaxf(mx1, __shfl_xor_sync(0xffffffffu, mx1, 1));
        mx1 = fmaxf(mx1, __shfl_xor_sync(0xffffffffu, mx1, 2));
        float mn0 = fmaxf(mrow0, mx0), mn1 = fmaxf(mrow1, mx1);
        float al0 = __expf(mrow0 - mn0), al1 = __expf(mrow1 - mn1);
        mrow0 = mn0; mrow1 = mn1;

        float rs0 = 0.f, rs1 = 0.f;
        #pragma unroll
        for (int nt = 0; nt < 8; nt++) {
            s[nt][0] = __expf(s[nt][0] - mn0);
            s[nt][1] = __expf(s[nt][1] - mn0);
            s[nt][2] = __expf(s[nt][2] - mn1);
            s[nt][3] = __expf(s[nt][3] - mn1);
            rs0 += s[nt][0] + s[nt][1];
            rs1 += s[nt][2] + s[nt][3];
        }
        rs0 += __shfl_xor_sync(0xffffffffu, rs0, 1);
        rs0 += __shfl_xor_sync(0xffffffffu, rs0, 2);
        rs1 += __shfl_xor_sync(0xffffffffu, rs1, 1);
        rs1 += __shfl_xor_sync(0xffffffffu, rs1, 2);
        lsum0 = lsum0 * al0 + rs0;
        lsum1 = lsum1 * al1 + rs1;

        // P -> smem (warp-private rows), relayout for A fragments
        int pr0 = wid * 16 + g, pr1 = pr0 + 8;
        #pragma unroll
        for (int nt = 0; nt < 8; nt++) {
            int cc = nt * 8 + 2 * tg;
            Ss[pr0 * SSTR + cc]     = s[nt][0];
            Ss[pr0 * SSTR + cc + 1] = s[nt][1];
            Ss[pr1 * SSTR + cc]     = s[nt][2];
            Ss[pr1 * SSTR + cc + 1] = s[nt][3];
        }
        __syncwarp();

        #pragma unroll
        for (int nt = 0; nt < 16; nt++) {
            o[nt][0] *= al0; o[nt][1] *= al0;
            o[nt][2] *= al1; o[nt][3] *= al1;
        }

        // O += P V
        #pragma unroll
        for (int ks = 0; ks < 8; ks++) {
            uint32_t pa[4];
            int pc = ks * 8 + tg;
            pa[0] = f2tf(Ss[pr0 * SSTR + pc]);
            pa[1] = f2tf(Ss[pr1 * SSTR + pc]);
            pa[2] = f2tf(Ss[pr0 * SSTR + pc + 4]);
            pa[3] = f2tf(Ss[pr1 * SSTR + pc + 4]);
            #pragma unroll
            for (int nt = 0; nt < 16; nt++) {
                int d = nt * 8 + g;
                int kk = ks * 8 + tg;
                uint32_t b0 = f2tf(Vs[kk * VSTR + d]);
                uint32_t b1 = f2tf(Vs[(kk + 4) * VSTR + d]);
                mma8(o[nt], pa, b0, b1);
            }
        }
    }

    float inv0 = 1.f / lsum0, inv1 = 1.f / lsum1;
    int t0 = q0 + wid * 16 + g;
    #pragma unroll
    for (int nt = 0; nt < 16; nt++) {
        int col = h * DHEAD + nt * 8 + 2 * tg;
        *(float2*)&aout[((size_t)b * SEQ + t0) * CDIM + col] =
            make_float2(o[nt][0] * inv0, o[nt][1] * inv0);
        *(float2*)&aout[((size_t)b * SEQ + t0 + 8) * CDIM + col] =
            make_float2(o[nt][2] * inv1, o[nt][3] * inv1);
    }
}

// ---------------------------------------------------------------------------
extern "C" void kernel_launch(void* const* d_in, const int* in_sizes, int n_in,
                              void* d_out, int out_size)
{
    const float* x  = (const float*)d_in[0];
    const float* Wq = (const float*)d_in[1];
    const float* bq = (const float*)d_in[2];
    const float* Wk = (const float*)d_in[3];
    const float* bk = (const float*)d_in[4];
    const float* Wv = (const float*)d_in[5];
    const float* bv = (const float*)d_in[6];
    const float* Wo = (const float*)d_in[7];
    const float* bo = (const float*)d_in[8];
    float* out = (float*)d_out;

    float *qp, *kp, *vp, *aop;
    cudaGetSymbolAddress((void**)&qp, g_q);
    cudaGetSymbolAddress((void**)&kp, g_k);
    cudaGetSymbolAddress((void**)&vp, g_v);
    cudaGetSymbolAddress((void**)&aop, g_ao);

    cudaFuncSetAttribute(attn_win, cudaFuncAttributeMaxDynamicSharedMemorySize, ATT_SMEM);

    const int M = BATCH * SEQ;      // 4096
    dim3 gg(M / GBM, CDIM / GBN);   // 32 x 16

    gemm_tf32<<<gg, 256>>>(x, Wq, bq, qp, M, CDIM, CDIM, 1);
    gemm_tf32<<<gg, 256>>>(x, Wk, bk, kp, M, CDIM, CDIM, 1);
    gemm_tf32<<<gg, 256>>>(x, Wv, bv, vp, M, CDIM, CDIM, 1);
    attn_win<<<dim3(SEQ / 128, BATCH * H_HEADS), 256, ATT_SMEM>>>(qp, kp, vp, aop);
    gemm_tf32<<<gg, 256>>>(aop, Wo, bo, out, M, CDIM, CDIM, 0);
}